// round 9
// baseline (speedup 1.0000x reference)
#include <cuda_runtime.h>

// Problem constants (fixed by the reference: N=16384, D=2, H=128)
constexpr int N_ROWS = 16384;
constexpr int H      = 128;
constexpr int NHi    = N_ROWS * H;          // floats per [N,H] tensor

constexpr int THREADS = 256;
constexpr int WPB     = 8;                           // warps per block
constexpr int BLOCKS  = 1024;
constexpr int TW      = BLOCKS * WPB;                // 8192 warps
constexpr int RPW     = N_ROWS / TW;                 // 2 rows/warp

// Persistent scratch (allocation-free __device__ globals). g_h / g_xnorm are
// fully overwritten each run; g_ysum/g_scalars/g_ticket are re-zeroed by the
// elected tail block so every graph replay starts clean.
__device__ float    g_h[N_ROWS];       // per-row: -N*||e||^2 + 10*diag
__device__ float    g_xnorm[N_ROWS];   // per-row: ||e||^2
__device__ float    g_ysum[H];         // sum_y bi_dec[y][c]
__device__ float    g_scalars[2];      // [0]=Synorm  [1]=sum diag
__device__ unsigned g_ticket;          // last-block election

__device__ __forceinline__ float warp_sum(float v) {
    #pragma unroll
    for (int o = 16; o > 0; o >>= 1) v += __shfl_down_sync(0xffffffffu, v, o);
    return v;
}

// ---------------------------------------------------------------------------
// Single kernel: barrier-free streaming pass (58.7 MB) + ticket-elected tail.
// The nce pass needs no re-read of bi_enc: per-row Cauchy-Schwarz bound
//   row_loss <= 5 - Synorm + h_r + 2*sqrt(xnorm_r * ||Ysum||^2)
// certifies relu(row_loss)=0; an exact fallback covers uncertified rows.
// ---------------------------------------------------------------------------
__global__ __launch_bounds__(THREADS) void fused_kernel(
    const float* __restrict__ enc, const float* __restrict__ dec,
    float* __restrict__ out)
{
    const int tid   = threadIdx.x;
    const int lane  = tid & 31;
    const int w     = tid >> 5;
    const int gwarp = blockIdx.x * WPB + w;

    // ---------------- streaming phase ----------------
    float ys0 = 0.f, ys1 = 0.f, ys2 = 0.f, ys3 = 0.f;
    float ynorm = 0.f, dgsum = 0.f;
    float hp[RPW], xp[RPW];

    #pragma unroll
    for (int i = 0; i < RPW; i++) {
        const int r = gwarp + i * TW;
        // row r = 256 floats = 64 float4; direction halves at +0 / +32
        const float4 a = __ldcs((const float4*)enc + r * 64 + lane);
        const float4 b = __ldcs((const float4*)enc + r * 64 + 32 + lane);
        const float4 c = __ldcs((const float4*)dec + r * 64 + lane);
        const float4 d = __ldcs((const float4*)dec + r * 64 + 32 + lane);

        float4 e; e.x = a.x + b.x; e.y = a.y + b.y; e.z = a.z + b.z; e.w = a.w + b.w;
        float4 f; f.x = c.x + d.x; f.y = c.y + d.y; f.z = c.z + d.z; f.w = c.w + d.w;

        __stcs((float4*)out +           r * 32 + lane, e);   // bi_enc
        __stcs((float4*)out + NHi / 4 + r * 32 + lane, e);   // bi_enc (again)
        __stcs((float4*)out + NHi / 2 + r * 32 + lane, f);   // bi_dec

        ys0 += f.x; ys1 += f.y; ys2 += f.z; ys3 += f.w;
        ynorm += f.x * f.x + f.y * f.y + f.z * f.z + f.w * f.w;

        const float en  = e.x * e.x + e.y * e.y + e.z * e.z + e.w * e.w;
        const float gx = e.x - f.x, gy = e.y - f.y, gz = e.z - f.z, gw = e.w - f.w;
        const float dgl = gx * gx + gy * gy + gz * gz + gw * gw;

        dgsum += dgl;
        xp[i] = en;
        hp[i] = fmaf(-(float)N_ROWS, en, 10.0f * dgl);
    }

    // Deferred reductions: 6 independent shfl chains, interleaved by ptxas.
    float h0 = hp[0], h1 = hp[1], x0 = xp[0], x1 = xp[1];
    #pragma unroll
    for (int o = 16; o > 0; o >>= 1) {
        h0    += __shfl_down_sync(0xffffffffu, h0, o);
        h1    += __shfl_down_sync(0xffffffffu, h1, o);
        x0    += __shfl_down_sync(0xffffffffu, x0, o);
        x1    += __shfl_down_sync(0xffffffffu, x1, o);
        ynorm += __shfl_down_sync(0xffffffffu, ynorm, o);
        dgsum += __shfl_down_sync(0xffffffffu, dgsum, o);
    }
    if (lane == 0) {
        g_h[gwarp]          = h0;
        g_h[gwarp + TW]     = h1;
        g_xnorm[gwarp]      = x0;
        g_xnorm[gwarp + TW] = x1;
    }

    __shared__ float s_ys[WPB][H];
    __shared__ float s_sc[WPB][2];
    s_ys[w][4 * lane + 0] = ys0;
    s_ys[w][4 * lane + 1] = ys1;
    s_ys[w][4 * lane + 2] = ys2;
    s_ys[w][4 * lane + 3] = ys3;
    if (lane == 0) { s_sc[w][0] = ynorm; s_sc[w][1] = dgsum; }
    __syncthreads();

    if (tid < H) {
        float s = 0.f;
        #pragma unroll
        for (int ww = 0; ww < WPB; ww++) s += s_ys[ww][tid];
        atomicAdd(&g_ysum[tid], s);
    } else if (tid == H) {
        float yn = 0.f, ds = 0.f;
        #pragma unroll
        for (int ww = 0; ww < WPB; ww++) { yn += s_sc[ww][0]; ds += s_sc[ww][1]; }
        atomicAdd(&g_scalars[0], yn);
        atomicAdd(&g_scalars[1], ds);
    }

    // ---------------- ticket election ----------------
    __shared__ unsigned s_last;
    __shared__ float s_stat[2];            // [0]=||Ysum||^2  [1]=Synorm
    __shared__ float s_ysm[H];             // Ysum, shared-resident for fallback
    __shared__ float s_part[WPB];
    if (tid == 0) {
        __threadfence();                   // my stores/atomics visible first
        s_last = (atomicAdd(&g_ticket, 1u) == BLOCKS - 1) ? 1u : 0u;
    }
    __syncthreads();
    if (!s_last) return;

    // ---------------- tail: runs in the last block only ----------------
    // All other blocks' fences precede their ticket increments, so every
    // g_h/g_xnorm store and g_ysum/g_scalars atomic is visible via L2.
    float v = (tid < H) ? __ldcg(&g_ysum[tid]) : 0.0f;
    if (tid < H) s_ysm[tid] = v;
    float ysq = warp_sum(v * v);
    if (lane == 0) s_part[w] = ysq;
    __syncthreads();
    if (tid == 0) {
        float t = 0.f;
        #pragma unroll
        for (int ww = 0; ww < WPB; ww++) t += s_part[ww];
        s_stat[0] = t;                      // ||Ysum||^2
        s_stat[1] = __ldcg(&g_scalars[0]);  // Synorm
    }
    __syncthreads();
    const float ysn2 = s_stat[0];
    const float syn  = s_stat[1];

    float nce = 0.f;
    #pragma unroll 8
    for (int i = 0; i < N_ROWS / THREADS; i++) {
        const int r = tid + i * THREADS;
        const float h  = __ldcg(&g_h[r]);
        const float xn = __ldcg(&g_xnorm[r]);
        const float base = 5.0f - syn + h;
        const float ub = base + 2.0f * sqrtf(xn * ysn2);   // Cauchy-Schwarz
        if (ub > 0.0f) {
            // Exact fallback (never taken on this data; correct in general).
            float dp = 0.f;
            for (int c4 = 0; c4 < 32; c4++) {
                const float4 e  = __ldcg((const float4*)out + r * 32 + c4);
                const float4 yv = ((const float4*)s_ysm)[c4];
                dp += e.x * yv.x + e.y * yv.y + e.z * yv.z + e.w * yv.w;
            }
            nce += fmaxf(fmaf(2.0f, dp, base), 0.0f);
        }
    }
    nce = warp_sum(nce);
    if (lane == 0) s_part[w] = nce;
    __syncthreads();

    if (tid == 0) {
        float tot = 0.f;
        #pragma unroll
        for (int ww = 0; ww < WPB; ww++) tot += s_part[ww];
        out[3 * NHi]     = tot;                                    // nce_loss
        out[3 * NHi + 1] = -__ldcg(&g_scalars[1]) / (float)N_ROWS; // diagonal_loss
    }
    // Re-zero persistent state for the next graph replay.
    if (tid < H) g_ysum[tid] = 0.0f;
    if (tid == H)     g_scalars[0] = 0.0f;
    if (tid == H + 1) g_scalars[1] = 0.0f;
    if (tid == H + 2) atomicExch(&g_ticket, 0u);
}

extern "C" void kernel_launch(void* const* d_in, const int* in_sizes, int n_in,
                              void* d_out, int out_size) {
    const float* enc = (const float*)d_in[0];
    const float* dec = (const float*)d_in[1];
    float* out = (float*)d_out;

    fused_kernel<<<BLOCKS, THREADS>>>(enc, dec, out);
}

// round 10
// speedup vs baseline: 1.9050x; 1.9050x over previous
#include <cuda_runtime.h>

// Problem constants (fixed by the reference: N=16384, D=2, H=128)
constexpr int N_ROWS = 16384;
constexpr int H      = 128;
constexpr int NHi    = N_ROWS * H;          // floats per [N,H] tensor

constexpr int THREADS = 256;
constexpr int WPB     = 8;                           // warps per block

// K1: streaming pass (best-known config from R7)
constexpr int BLOCKS1 = 1024;
constexpr int TW1     = BLOCKS1 * WPB;               // 8192 warps
constexpr int RPW1    = N_ROWS / TW1;                // 2 rows/warp

// K2: certificate pass — one row per thread, 128 KB total traffic
constexpr int BLOCKS2 = N_ROWS / THREADS;            // 64 blocks

// Persistent scratch (allocation-free __device__ globals). g_h/g_xnorm are
// fully overwritten each run; the rest re-zeroed by K2's elected last block.
__device__ float    g_h[N_ROWS];       // per-row: -N*||e||^2 + 10*diag
__device__ float    g_xnorm[N_ROWS];   // per-row: ||e||^2
__device__ float    g_ysum[H];         // sum_y bi_dec[y][c]
__device__ float    g_scalars[3];      // [0]=Synorm  [1]=sum diag  [2]=nce
__device__ unsigned g_ticket;          // last-block election (K2)

__device__ __forceinline__ float warp_sum(float v) {
    #pragma unroll
    for (int o = 16; o > 0; o >>= 1) v += __shfl_down_sync(0xffffffffu, v, o);
    return v;
}

// ---------------------------------------------------------------------------
// K1: stream enc+dec once (33.5 MB in, 25.2 MB out). Identical to the best
// 18.9us configuration, plus a per-row xnorm store for K2's certificate.
// ---------------------------------------------------------------------------
__global__ __launch_bounds__(THREADS) void stream_kernel(
    const float* __restrict__ enc, const float* __restrict__ dec,
    float* __restrict__ out)
{
    const int tid   = threadIdx.x;
    const int lane  = tid & 31;
    const int w     = tid >> 5;
    const int gwarp = blockIdx.x * WPB + w;

    float ys0 = 0.f, ys1 = 0.f, ys2 = 0.f, ys3 = 0.f;
    float ynorm = 0.f, dgsum = 0.f;
    float hp[RPW1], xp[RPW1];

    #pragma unroll
    for (int i = 0; i < RPW1; i++) {
        const int r = gwarp + i * TW1;
        // row r = 256 floats = 64 float4; direction halves at +0 / +32
        const float4 a = __ldg((const float4*)enc + r * 64 + lane);
        const float4 b = __ldg((const float4*)enc + r * 64 + 32 + lane);
        const float4 c = __ldg((const float4*)dec + r * 64 + lane);
        const float4 d = __ldg((const float4*)dec + r * 64 + 32 + lane);

        float4 e; e.x = a.x + b.x; e.y = a.y + b.y; e.z = a.z + b.z; e.w = a.w + b.w;
        float4 f; f.x = c.x + d.x; f.y = c.y + d.y; f.z = c.z + d.z; f.w = c.w + d.w;

        ((float4*)out)[r * 32 + lane] = e;                   // bi_enc
        __stcs((float4*)out + NHi / 4 + r * 32 + lane, e);   // bi_enc copy
        __stcs((float4*)out + NHi / 2 + r * 32 + lane, f);   // bi_dec

        ys0 += f.x; ys1 += f.y; ys2 += f.z; ys3 += f.w;
        ynorm += f.x * f.x + f.y * f.y + f.z * f.z + f.w * f.w;

        const float en  = e.x * e.x + e.y * e.y + e.z * e.z + e.w * e.w;
        const float gx = e.x - f.x, gy = e.y - f.y, gz = e.z - f.z, gw = e.w - f.w;
        const float dgl = gx * gx + gy * gy + gz * gz + gw * gw;

        dgsum += dgl;
        xp[i] = en;
        hp[i] = fmaf(-(float)N_ROWS, en, 10.0f * dgl);
    }

    // Deferred reductions: 6 independent shfl chains, interleaved by ptxas.
    float h0 = hp[0], h1 = hp[1], x0 = xp[0], x1 = xp[1];
    #pragma unroll
    for (int o = 16; o > 0; o >>= 1) {
        h0    += __shfl_down_sync(0xffffffffu, h0, o);
        h1    += __shfl_down_sync(0xffffffffu, h1, o);
        x0    += __shfl_down_sync(0xffffffffu, x0, o);
        x1    += __shfl_down_sync(0xffffffffu, x1, o);
        ynorm += __shfl_down_sync(0xffffffffu, ynorm, o);
        dgsum += __shfl_down_sync(0xffffffffu, dgsum, o);
    }
    if (lane == 0) {
        g_h[gwarp]           = h0;
        g_h[gwarp + TW1]     = h1;
        g_xnorm[gwarp]       = x0;
        g_xnorm[gwarp + TW1] = x1;
    }

    __shared__ float s_ys[WPB][H];
    __shared__ float s_sc[WPB][2];
    s_ys[w][4 * lane + 0] = ys0;
    s_ys[w][4 * lane + 1] = ys1;
    s_ys[w][4 * lane + 2] = ys2;
    s_ys[w][4 * lane + 3] = ys3;
    if (lane == 0) { s_sc[w][0] = ynorm; s_sc[w][1] = dgsum; }
    __syncthreads();

    if (tid < H) {
        float s = 0.f;
        #pragma unroll
        for (int ww = 0; ww < WPB; ww++) s += s_ys[ww][tid];
        atomicAdd(&g_ysum[tid], s);
    } else if (tid == H) {
        float yn = 0.f, ds = 0.f;
        #pragma unroll
        for (int ww = 0; ww < WPB; ww++) { yn += s_sc[ww][0]; ds += s_sc[ww][1]; }
        atomicAdd(&g_scalars[0], yn);
        atomicAdd(&g_scalars[1], ds);
    }
}

// ---------------------------------------------------------------------------
// K2: nce via per-row Cauchy-Schwarz certificate. Touches ONLY 128 KB of
// __device__ scratch (never the freshly-written d_out, except in the exact
// fallback, which is provably dormant on this data but correct in general).
// One row per thread; last block (ticket) writes scalars and re-zeros state.
// ---------------------------------------------------------------------------
__global__ __launch_bounds__(THREADS) void nce_kernel(float* __restrict__ out)
{
    const int tid  = threadIdx.x;
    const int lane = tid & 31;
    const int w    = tid >> 5;
    const int r    = blockIdx.x * THREADS + tid;     // one row per thread

    __shared__ float s_ysm[H];
    __shared__ float s_part[WPB];
    __shared__ float s_stat[2];

    // Per-block: load Ysum into shared, reduce ||Ysum||^2 (128 KB-free: 512 B)
    float v = (tid < H) ? g_ysum[tid] : 0.0f;
    if (tid < H) s_ysm[tid] = v;
    float ysq = warp_sum(v * v);
    if (lane == 0) s_part[w] = ysq;
    __syncthreads();
    if (tid == 0) {
        float t = 0.f;
        #pragma unroll
        for (int ww = 0; ww < WPB; ww++) t += s_part[ww];
        s_stat[0] = t;                 // ||Ysum||^2
        s_stat[1] = g_scalars[0];      // Synorm
    }
    __syncthreads();
    const float ysn2 = s_stat[0];
    const float syn  = s_stat[1];

    // Certificate: row_loss <= base + 2*sqrt(xnorm*||Ysum||^2). Slack absorbs
    // fp32 rounding (margin on this data is ~8e6; slack is ~1e2).
    const float h    = g_h[r];
    const float xn   = g_xnorm[r];
    const float base = 5.0f - syn + h;
    const float ub   = base + 2.0f * sqrtf(xn * ysn2)
                     + 16.0f + 1e-5f * (fabsf(h) + fabsf(syn));

    float nce = 0.0f;
    if (ub > 0.0f) {
        // Exact fallback: dot this row of bi_enc with Ysum (shared-resident).
        float dp = 0.f;
        for (int c4 = 0; c4 < 32; c4++) {
            const float4 e  = __ldg((const float4*)out + r * 32 + c4);
            const float4 yv = ((const float4*)s_ysm)[c4];
            dp += e.x * yv.x + e.y * yv.y + e.z * yv.z + e.w * yv.w;
        }
        nce = fmaxf(fmaf(2.0f, dp, base), 0.0f);
    }

    nce = warp_sum(nce);
    if (lane == 0) s_part[w] = nce;
    __syncthreads();

    if (tid == 0) {
        float tn = 0.f;
        #pragma unroll
        for (int ww = 0; ww < WPB; ww++) tn += s_part[ww];
        atomicAdd(&g_scalars[2], tn);
        __threadfence();
        // Last-arriving block writes outputs and re-zeros persistent state.
        if (atomicAdd(&g_ticket, 1u) == BLOCKS2 - 1) {
            const float nce_t = atomicAdd(&g_scalars[2], 0.0f);
            const float diag  = g_scalars[1];
            out[3 * NHi]     = nce_t;                      // nce_loss
            out[3 * NHi + 1] = -diag / (float)N_ROWS;      // diagonal_loss
            #pragma unroll
            for (int i = 0; i < H; i++) g_ysum[i] = 0.0f;
            g_scalars[0] = 0.0f; g_scalars[1] = 0.0f; g_scalars[2] = 0.0f;
            atomicExch(&g_ticket, 0u);
        }
    }
}

extern "C" void kernel_launch(void* const* d_in, const int* in_sizes, int n_in,
                              void* d_out, int out_size) {
    const float* enc = (const float*)d_in[0];
    const float* dec = (const float*)d_in[1];
    float* out = (float*)d_out;

    stream_kernel<<<BLOCKS1, THREADS>>>(enc, dec, out);
    nce_kernel<<<BLOCKS2, THREADS>>>(out);
}